// round 1
// baseline (speedup 1.0000x reference)
#include <cuda_runtime.h>
#include <mma.h>

using namespace nvcuda;

#define N_NODES   100000
#define NODES_PAD 100032            // 1563 * 64
#define N_EDGES   1600000
#define HID       128
#define NGRAPH    1024
#define LN_EPS    1e-5f
#define SCAN_PAD  100352            // 98 * 1024

// ---------------- scratch (static __device__, allocation-free) ----------------
__device__ float  g_h[NODES_PAD * HID];    // node features (fp32, in-place LN update)
__device__ float  g_u[NODES_PAD * HID];    // agg + h  (GEMM1 input); pad rows stay 0
__device__ float  g_t[NODES_PAD * HID];    // relu(u@w1+b1) (GEMM2 input); pad rows stay 0
__device__ float4 g_rec[N_EDGES];          // per-edge packed: ea0,ea1,ea2,src(bits)
__device__ int    g_deg[N_NODES];
__device__ int    g_inc[SCAN_PAD];
__device__ int    g_bsum[128];
__device__ int    g_boff[128];
__device__ int    g_rowptr[N_NODES + 1];
__device__ int    g_cursor[N_NODES];
__device__ float  g_pooled[NGRAPH * HID];

// ---------------- CSR build ----------------
__global__ void k_zero() {
    int i = blockIdx.x * blockDim.x + threadIdx.x;
    if (i < N_NODES) { g_deg[i] = 0; g_cursor[i] = 0; }
}

__global__ void k_hist(const int* __restrict__ ei) {
    int e = blockIdx.x * blockDim.x + threadIdx.x;
    if (e < N_EDGES) atomicAdd(&g_deg[ei[N_EDGES + e]], 1);
}

__global__ void k_scanA() {
    __shared__ int s[1024];
    int t = threadIdx.x;
    int i = blockIdx.x * 1024 + t;
    int v = (i < N_NODES) ? g_deg[i] : 0;
    s[t] = v;
    __syncthreads();
    for (int off = 1; off < 1024; off <<= 1) {
        int w = (t >= off) ? s[t - off] : 0;
        __syncthreads();
        s[t] += w;
        __syncthreads();
    }
    g_inc[i] = s[t];
    if (t == 1023) g_bsum[blockIdx.x] = s[1023];
}

__global__ void k_scanB() {
    int acc = 0;
    for (int b = 0; b < 98; b++) { g_boff[b] = acc; acc += g_bsum[b]; }
}

__global__ void k_scanC() {
    int i = blockIdx.x * blockDim.x + threadIdx.x;
    if (i < N_NODES) {
        g_rowptr[i + 1] = g_inc[i] + g_boff[i >> 10];
        if (i == 0) g_rowptr[0] = 0;
    }
}

__global__ void k_scatter(const int* __restrict__ ei, const float* __restrict__ ea) {
    int e = blockIdx.x * blockDim.x + threadIdx.x;
    if (e >= N_EDGES) return;
    int s = ei[e];
    int d = ei[N_EDGES + e];
    int p = g_rowptr[d] + atomicAdd(&g_cursor[d], 1);
    const float* a = ea + (long long)e * 3;
    g_rec[p] = make_float4(a[0], a[1], a[2], __int_as_float(s));
}

// ---------------- input projection: h = x @ inW + inb ----------------
__global__ void k_inproj(const float* __restrict__ x, const float* __restrict__ inW,
                         const float* __restrict__ inb) {
    int idx = blockIdx.x * blockDim.x + threadIdx.x;
    if (idx >= N_NODES * HID) return;
    int n = idx >> 7, j = idx & 127;
    const float* xr = x + n * 7;
    float s = inb[j];
#pragma unroll
    for (int k = 0; k < 7; k++) s = fmaf(xr[k], inW[k * HID + j], s);
    g_h[idx] = s;
}

// ---------------- edge aggregation (one warp per node, zero atomics) ----------------
// u[n] = h[n] + sum_{e: dst=n} relu( h[src_e] + edge_attr_e @ edgeW + edgeb )
__global__ void k_edge_agg(const float* __restrict__ edgeW_l, const float* __restrict__ edgeb_l) {
    __shared__ float sw[512];   // W rows k=0..2 at [k*128+j], bias at [384+j]
    for (int i = threadIdx.x; i < 512; i += blockDim.x)
        sw[i] = (i < 384) ? edgeW_l[i] : edgeb_l[i - 384];
    __syncthreads();

    int warp = threadIdx.x >> 5, lane = threadIdx.x & 31;
    int n = blockIdx.x * 8 + warp;
    if (n >= N_NODES) return;

    int r0 = g_rowptr[n], r1 = g_rowptr[n + 1];
    float acc[4];
#pragma unroll
    for (int q = 0; q < 4; q++) acc[q] = g_h[n * HID + lane + 32 * q];

    for (int e = r0; e < r1; e++) {
        float4 rec = g_rec[e];                 // broadcast within warp
        int src = __float_as_int(rec.w);
        const float* hs = g_h + src * HID;
#pragma unroll
        for (int q = 0; q < 4; q++) {
            int j = lane + 32 * q;
            float m = fmaf(rec.x, sw[j],
                      fmaf(rec.y, sw[128 + j],
                      fmaf(rec.z, sw[256 + j], sw[384 + j])));
            m += hs[j];
            acc[q] += fmaxf(m, 0.f);
        }
    }
#pragma unroll
    for (int q = 0; q < 4; q++) g_u[n * HID + lane + 32 * q] = acc[q];
}

// ---------------- GEMM1: t = relu(u @ w1 + b1)  (tf32 WMMA) ----------------
__global__ void k_gemm_relu(const float* __restrict__ W, const float* __restrict__ bias) {
    int warp = threadIdx.x >> 5, lane = threadIdx.x & 31;
    int row0 = blockIdx.x * 64 + warp * 16;

    wmma::fragment<wmma::accumulator, 16, 16, 8, float> acc[8];
#pragma unroll
    for (int n = 0; n < 8; n++) wmma::fill_fragment(acc[n], 0.f);

    wmma::fragment<wmma::matrix_a, 16, 16, 8, wmma::precision::tf32, wmma::row_major> a;
    wmma::fragment<wmma::matrix_b, 16, 16, 8, wmma::precision::tf32, wmma::row_major> b;

    for (int k0 = 0; k0 < HID; k0 += 8) {
        wmma::load_matrix_sync(a, g_u + row0 * HID + k0, HID);
#pragma unroll
        for (int i = 0; i < a.num_elements; i++) a.x[i] = wmma::__float_to_tf32(a.x[i]);
#pragma unroll
        for (int n = 0; n < 8; n++) {
            wmma::load_matrix_sync(b, W + k0 * HID + n * 16, HID);
#pragma unroll
            for (int i = 0; i < b.num_elements; i++) b.x[i] = wmma::__float_to_tf32(b.x[i]);
            wmma::mma_sync(acc[n], a, b, acc[n]);
        }
    }

    __shared__ float stage[4][256];
    for (int n = 0; n < 8; n++) {
        wmma::store_matrix_sync(stage[warp], acc[n], 16, wmma::mem_row_major);
        __syncwarp();
#pragma unroll
        for (int r = 0; r < 8; r++) {
            int e = lane + 32 * r;
            int rr = e >> 4, cc = e & 15;
            int grow = row0 + rr, gcol = n * 16 + cc;
            if (grow < N_NODES)
                g_t[grow * HID + gcol] = fmaxf(stage[warp][e] + bias[gcol], 0.f);
        }
        __syncwarp();
    }
}

// ---------------- GEMM2 + residual + LayerNorm (in-place h update) ----------------
__global__ void k_gemm_ln(const float* __restrict__ W, const float* __restrict__ bias,
                          const float* __restrict__ gamma, const float* __restrict__ beta) {
    int warp = threadIdx.x >> 5, lane = threadIdx.x & 31;
    int row0 = blockIdx.x * 64 + warp * 16;

    wmma::fragment<wmma::accumulator, 16, 16, 8, float> acc[8];
#pragma unroll
    for (int n = 0; n < 8; n++) wmma::fill_fragment(acc[n], 0.f);

    wmma::fragment<wmma::matrix_a, 16, 16, 8, wmma::precision::tf32, wmma::row_major> a;
    wmma::fragment<wmma::matrix_b, 16, 16, 8, wmma::precision::tf32, wmma::row_major> b;

    for (int k0 = 0; k0 < HID; k0 += 8) {
        wmma::load_matrix_sync(a, g_t + row0 * HID + k0, HID);
#pragma unroll
        for (int i = 0; i < a.num_elements; i++) a.x[i] = wmma::__float_to_tf32(a.x[i]);
#pragma unroll
        for (int n = 0; n < 8; n++) {
            wmma::load_matrix_sync(b, W + k0 * HID + n * 16, HID);
#pragma unroll
            for (int i = 0; i < b.num_elements; i++) b.x[i] = wmma::__float_to_tf32(b.x[i]);
            wmma::mma_sync(acc[n], a, b, acc[n]);
        }
    }

    __shared__ float stage[4][16 * HID];
#pragma unroll
    for (int n = 0; n < 8; n++)
        wmma::store_matrix_sync(&stage[warp][n * 16], acc[n], HID, wmma::mem_row_major);
    __syncwarp();

    for (int r = 0; r < 16; r++) {
        int grow = row0 + r;
        if (grow >= N_NODES) break;
        float v[4];
        float s = 0.f, s2 = 0.f;
#pragma unroll
        for (int q = 0; q < 4; q++) {
            int j = lane + 32 * q;
            float gg = stage[warp][r * HID + j] + bias[j];
            float val = g_h[grow * HID + j] + fmaxf(gg, 0.f);
            v[q] = val; s += val; s2 += val * val;
        }
#pragma unroll
        for (int off = 16; off; off >>= 1) {
            s  += __shfl_xor_sync(0xffffffffu, s, off);
            s2 += __shfl_xor_sync(0xffffffffu, s2, off);
        }
        float mu = s * (1.f / HID);
        float var = s2 * (1.f / HID) - mu * mu;
        float rstd = rsqrtf(var + LN_EPS);
#pragma unroll
        for (int q = 0; q < 4; q++) {
            int j = lane + 32 * q;
            g_h[grow * HID + j] = (v[q] - mu) * rstd * gamma[j] + beta[j];
        }
    }
}

// ---------------- global mean pool (batch sorted -> binary search) ----------------
__device__ __forceinline__ int lbound(const int* a, int n, int key) {
    int lo = 0, hi = n;
    while (lo < hi) { int m = (lo + hi) >> 1; if (a[m] < key) lo = m + 1; else hi = m; }
    return lo;
}

__global__ void k_pool(const int* __restrict__ batch) {
    int g = blockIdx.x, t = threadIdx.x;
    __shared__ int slo, shi;
    if (t == 0) { slo = lbound(batch, N_NODES, g); shi = lbound(batch, N_NODES, g + 1); }
    __syncthreads();
    int lo = slo, hi = shi;
    float s = 0.f;
    for (int n = lo; n < hi; n++) s += g_h[n * HID + t];
    float cnt = (float)(hi - lo);
    g_pooled[g * HID + t] = s / fmaxf(cnt, 1.f);
}

// ---------------- MLP head ----------------
__global__ void k_head(const float* __restrict__ W1, const float* __restrict__ b1,
                       const float* __restrict__ W2, const float* __restrict__ b2,
                       const float* __restrict__ W3, const float* __restrict__ b3,
                       float* __restrict__ out) {
    int g = blockIdx.x, t = threadIdx.x;
    __shared__ float p[HID], o1[HID], o2[64], red[64];
    p[t] = g_pooled[g * HID + t];
    __syncthreads();
    float s = b1[t];
    for (int k = 0; k < HID; k++) s = fmaf(p[k], W1[k * HID + t], s);
    o1[t] = fmaxf(s, 0.f);
    __syncthreads();
    if (t < 64) {
        float s2 = b2[t];
        for (int k = 0; k < HID; k++) s2 = fmaf(o1[k], W2[k * 64 + t], s2);
        o2[t] = fmaxf(s2, 0.f);
    }
    __syncthreads();
    if (t < 64) red[t] = o2[t] * W3[t];
    __syncthreads();
    if (t < 32) {
        float v = red[t] + red[t + 32];
#pragma unroll
        for (int off = 16; off; off >>= 1) v += __shfl_down_sync(0xffffffffu, v, off);
        if (t == 0) out[g] = v + b3[0];
    }
}

// ---------------- launch ----------------
extern "C" void kernel_launch(void* const* d_in, const int* in_sizes, int n_in,
                              void* d_out, int out_size) {
    const float* x     = (const float*)d_in[0];
    const int*   ei    = (const int*)  d_in[1];
    const float* ea    = (const float*)d_in[2];
    const int*   batch = (const int*)  d_in[3];
    const float* inW   = (const float*)d_in[4];
    const float* inb   = (const float*)d_in[5];
    const float* edgeW = (const float*)d_in[6];
    const float* edgeb = (const float*)d_in[7];
    const float* w1    = (const float*)d_in[8];
    const float* b1    = (const float*)d_in[9];
    const float* w2    = (const float*)d_in[10];
    const float* b2    = (const float*)d_in[11];
    const float* gamma = (const float*)d_in[12];
    const float* beta  = (const float*)d_in[13];
    const float* fcW1  = (const float*)d_in[14];
    const float* fcb1  = (const float*)d_in[15];
    const float* fcW2  = (const float*)d_in[16];
    const float* fcb2  = (const float*)d_in[17];
    const float* fcW3  = (const float*)d_in[18];
    const float* fcb3  = (const float*)d_in[19];
    float* out = (float*)d_out;

    k_zero<<<(N_NODES + 255) / 256, 256>>>();
    k_hist<<<(N_EDGES + 255) / 256, 256>>>(ei);
    k_scanA<<<98, 1024>>>();
    k_scanB<<<1, 1>>>();
    k_scanC<<<(N_NODES + 255) / 256, 256>>>();
    k_scatter<<<(N_EDGES + 255) / 256, 256>>>(ei, ea);
    k_inproj<<<(N_NODES * HID + 255) / 256, 256>>>(x, inW, inb);

    for (int l = 0; l < 4; l++) {
        k_edge_agg<<<(N_NODES + 7) / 8, 256>>>(edgeW + l * 3 * HID, edgeb + l * HID);
        k_gemm_relu<<<NODES_PAD / 64, 128>>>(w1 + l * HID * HID, b1 + l * HID);
        k_gemm_ln<<<NODES_PAD / 64, 128>>>(w2 + l * HID * HID, b2 + l * HID,
                                           gamma + l * HID, beta + l * HID);
    }

    k_pool<<<NGRAPH, 128>>>(batch);
    k_head<<<NGRAPH, 128>>>(fcW1, fcb1, fcW2, fcb2, fcW3, fcb3, out);
}